// round 3
// baseline (speedup 1.0000x reference)
#include <cuda_runtime.h>
#include <stdint.h>

#define N_ITERS 40
#define BATCH   128
#define T_TOK   32768
#define D_FEAT  128   // floats per row = 32 float4

// Scratch: per-iteration inclusive cumsum of segment sizes (segment end offsets).
__device__ int g_ends[N_ITERS * BATCH];

// Robust to sizes being stored as int32 (jax default, x64 off) or int64.
__global__ void compute_ends_kernel(const void* __restrict__ sizes_raw) {
    int n = blockIdx.x * blockDim.x + threadIdx.x;
    if (n >= N_ITERS) return;

    const int*       s32 = (const int*)sizes_raw;
    const long long* s64 = (const long long*)sizes_raw;

    // Probe: does the int32 interpretation of this row sum to T?
    long long probe = 0;
    for (int i = 0; i < BATCH; ++i) probe += s32[n * BATCH + i];
    const bool is32 = (probe == T_TOK);

    long long acc = 0;
    for (int i = 0; i < BATCH; ++i) {
        acc += is32 ? (long long)s32[n * BATCH + i] : s64[(size_t)n * BATCH + i];
        g_ends[n * BATCH + i] = (int)acc;
    }
}

// One warp per token row. 8 rows per 256-thread block.
__global__ __launch_bounds__(256) void seg_reverse_gather_kernel(
    const float4* __restrict__ data, float4* __restrict__ out) {
    __shared__ int s_ends[BATCH];

    const int n = blockIdx.y;
    if (threadIdx.x < BATCH)
        s_ends[threadIdx.x] = g_ends[n * BATCH + threadIdx.x];
    __syncthreads();

    const int warp = threadIdx.x >> 5;
    const int lane = threadIdx.x & 31;
    const int t = (blockIdx.x << 3) + warp;   // token row in [0, T)

    // searchsorted(ends, t, side='right'): smallest seg with ends[seg] > t.
    // Answer lies in [0, 128] -> 129 candidates -> need 8 bisection steps.
    // (Steps past convergence are no-ops: predicate at the answer is true.)
    int lo = 0, hi = BATCH;
    #pragma unroll
    for (int step = 0; step < 8; ++step) {
        int mid = (lo + hi) >> 1;
        if (s_ends[mid] > t) hi = mid; else lo = mid + 1;
    }
    const int seg   = (lo < BATCH) ? lo : (BATCH - 1);
    const int end   = s_ends[seg];
    const int start = seg ? s_ends[seg - 1] : 0;
    int src = start + end - 1 - t;
    // Defensive clamp: any logic error becomes a wrong value, not a fault.
    src = src < 0 ? 0 : (src >= T_TOK ? T_TOK - 1 : src);

    const size_t base = (size_t)n * T_TOK;
    // Row = 128 floats = 32 float4; lane l moves float4 l. Fully coalesced.
    out[(base + (size_t)t) * 32 + lane] = data[(base + (size_t)src) * 32 + lane];
}

extern "C" void kernel_launch(void* const* d_in, const int* in_sizes, int n_in,
                              void* d_out, int out_size) {
    // Identify which input is `sizes` (N_ITERS*BATCH elements) vs `data`.
    const void*   sizes = d_in[0];
    const float4* data  = (const float4*)d_in[1];
    if (n_in >= 2 && in_sizes[0] != N_ITERS * BATCH) {
        sizes = d_in[1];
        data  = (const float4*)d_in[0];
    }
    float4* out = (float4*)d_out;

    compute_ends_kernel<<<1, 64>>>(sizes);

    dim3 grid(T_TOK / 8, N_ITERS);
    seg_reverse_gather_kernel<<<grid, 256>>>(data, out);
}

// round 4
// speedup vs baseline: 1.1570x; 1.1570x over previous
#include <cuda_runtime.h>
#include <stdint.h>

#define N_ITERS 40
#define BATCH   128
#define T_TOK   32768
#define ROWS_PER_BLOCK 32
#define ROWS_PER_WARP  4

// Scratch: per-iteration inclusive cumsum of segment sizes (segment end offsets).
__device__ int g_ends[N_ITERS * BATCH];

// Robust to sizes being stored as int32 (jax default, x64 off) or int64.
__global__ void compute_ends_kernel(const void* __restrict__ sizes_raw) {
    int n = blockIdx.x * blockDim.x + threadIdx.x;
    if (n >= N_ITERS) return;

    const int*       s32 = (const int*)sizes_raw;
    const long long* s64 = (const long long*)sizes_raw;

    long long probe = 0;
    for (int i = 0; i < BATCH; ++i) probe += s32[n * BATCH + i];
    const bool is32 = (probe == T_TOK);

    long long acc = 0;
    for (int i = 0; i < BATCH; ++i) {
        acc += is32 ? (long long)s32[n * BATCH + i] : s64[(size_t)n * BATCH + i];
        g_ends[n * BATCH + i] = (int)acc;
    }
}

// 256 threads/block; block moves 32 token rows (16 KB). Warp 0 computes the
// 32 source indices (one binary search per lane); then each of the 8 warps
// moves 4 rows with 4 independent LDG.128 in flight.
__global__ __launch_bounds__(256) void seg_reverse_gather_kernel(
    const float4* __restrict__ data, float4* __restrict__ out) {
    __shared__ int s_ends[BATCH];
    __shared__ int s_src[ROWS_PER_BLOCK];

    const int n   = blockIdx.y;
    const int tid = threadIdx.x;
    if (tid < BATCH) s_ends[tid] = g_ends[n * BATCH + tid];
    __syncthreads();

    const int row0 = blockIdx.x * ROWS_PER_BLOCK;

    if (tid < ROWS_PER_BLOCK) {
        const int t = row0 + tid;
        // searchsorted(ends, t, 'right'): answer in [0,128] -> 8 bisect steps.
        int lo = 0, hi = BATCH;
        #pragma unroll
        for (int s = 0; s < 8; ++s) {
            int mid = (lo + hi) >> 1;
            if (s_ends[mid] > t) hi = mid; else lo = mid + 1;
        }
        const int seg   = (lo < BATCH) ? lo : (BATCH - 1);
        const int end   = s_ends[seg];
        const int start = seg ? s_ends[seg - 1] : 0;
        int src = start + end - 1 - t;
        src = src < 0 ? 0 : (src >= T_TOK ? T_TOK - 1 : src);
        s_src[tid] = src;
    }
    __syncthreads();

    const int warp = tid >> 5;
    const int lane = tid & 31;
    const size_t base = (size_t)n * T_TOK;
    const int r = warp * ROWS_PER_WARP;

    int src0 = s_src[r + 0];
    int src1 = s_src[r + 1];
    int src2 = s_src[r + 2];
    int src3 = s_src[r + 3];

    // 4 independent 512B row reads in flight, then 4 streaming writes.
    float4 v0 = __ldcs(&data[(base + (size_t)src0) * 32 + lane]);
    float4 v1 = __ldcs(&data[(base + (size_t)src1) * 32 + lane]);
    float4 v2 = __ldcs(&data[(base + (size_t)src2) * 32 + lane]);
    float4 v3 = __ldcs(&data[(base + (size_t)src3) * 32 + lane]);

    const size_t o = (base + (size_t)(row0 + r)) * 32 + lane;
    __stcs(&out[o +  0], v0);
    __stcs(&out[o + 32], v1);
    __stcs(&out[o + 64], v2);
    __stcs(&out[o + 96], v3);
}

extern "C" void kernel_launch(void* const* d_in, const int* in_sizes, int n_in,
                              void* d_out, int out_size) {
    // Identify which input is `sizes` (N_ITERS*BATCH elements) vs `data`.
    const void*   sizes = d_in[0];
    const float4* data  = (const float4*)d_in[1];
    if (n_in >= 2 && in_sizes[0] != N_ITERS * BATCH) {
        sizes = d_in[1];
        data  = (const float4*)d_in[0];
    }
    float4* out = (float4*)d_out;

    compute_ends_kernel<<<1, 64>>>(sizes);

    dim3 grid(T_TOK / ROWS_PER_BLOCK, N_ITERS);
    seg_reverse_gather_kernel<<<grid, 256>>>(data, out);
}

// round 5
// speedup vs baseline: 1.2226x; 1.0567x over previous
#include <cuda_runtime.h>
#include <stdint.h>

#define N_ITERS 40
#define BATCH   128
#define T_TOK   32768
#define ROWS_PER_BLOCK 64
#define ROWS_PER_WARP  8

// Scratch: per-iteration inclusive cumsum of segment sizes (segment end offsets).
__device__ int g_ends[N_ITERS * BATCH];

// Block-wide inclusive scan of 128 ints (4 warps): returns scanned value for
// this thread; total (thread 127's value) broadcast via smem.
__device__ __forceinline__ int block_scan128(int v, int tid, int* s_warp, int* total) {
    const int lane = tid & 31, warp = tid >> 5;
    #pragma unroll
    for (int d = 1; d < 32; d <<= 1) {
        int u = __shfl_up_sync(0xffffffffu, v, d);
        if (lane >= d) v += u;
    }
    if (lane == 31) s_warp[warp] = v;
    __syncthreads();
    int add = 0;
    if (warp > 0) {
        #pragma unroll
        for (int w = 0; w < 3; ++w) if (w < warp) add += s_warp[w];
    }
    v += add;
    __syncthreads();
    if (tid == 127) s_warp[4] = v;
    __syncthreads();
    *total = s_warp[4];
    __syncthreads();
    return v;
}

// One block per iteration row: parallel inclusive scan of 128 segment sizes.
// Robust to sizes stored as int32 (jax default, x64 off) or int64.
__global__ __launch_bounds__(128) void compute_ends_kernel(const void* __restrict__ sizes_raw) {
    __shared__ int s_warp[5];
    const int n   = blockIdx.x;
    const int tid = threadIdx.x;

    const int*       s32 = (const int*)sizes_raw;
    const long long* s64 = (const long long*)sizes_raw;

    int total;
    int e = block_scan128(s32[n * BATCH + tid], tid, s_warp, &total);
    if (total != T_TOK) {
        // int64 layout: rescan using the low word of each 8-byte element.
        e = block_scan128((int)s64[(size_t)n * BATCH + tid], tid, s_warp, &total);
    }
    g_ends[n * BATCH + tid] = e;
}

// 256 threads/block; block moves 64 token rows (32 KB). Threads 0..63 compute
// the 64 source indices (one binary search each); each of the 8 warps then
// moves 8 rows with 8 independent LDG.128 in flight.
__global__ __launch_bounds__(256) void seg_reverse_gather_kernel(
    const float4* __restrict__ data, float4* __restrict__ out) {
    __shared__ int s_ends[BATCH];
    __shared__ int s_src[ROWS_PER_BLOCK];

    const int n   = blockIdx.y;
    const int tid = threadIdx.x;
    if (tid < BATCH) s_ends[tid] = g_ends[n * BATCH + tid];
    __syncthreads();

    const int row0 = blockIdx.x * ROWS_PER_BLOCK;

    if (tid < ROWS_PER_BLOCK) {
        const int t = row0 + tid;
        // searchsorted(ends, t, 'right'): answer in [0,128] -> 8 bisect steps.
        int lo = 0, hi = BATCH;
        #pragma unroll
        for (int s = 0; s < 8; ++s) {
            int mid = (lo + hi) >> 1;
            if (s_ends[mid] > t) hi = mid; else lo = mid + 1;
        }
        const int seg   = (lo < BATCH) ? lo : (BATCH - 1);
        const int end   = s_ends[seg];
        const int start = seg ? s_ends[seg - 1] : 0;
        int src = start + end - 1 - t;
        src = src < 0 ? 0 : (src >= T_TOK ? T_TOK - 1 : src);
        s_src[tid] = src;
    }
    __syncthreads();

    const int warp = tid >> 5;
    const int lane = tid & 31;
    const size_t base = (size_t)n * T_TOK;
    const int r = warp * ROWS_PER_WARP;

    float4 v[ROWS_PER_WARP];
    #pragma unroll
    for (int i = 0; i < ROWS_PER_WARP; ++i)
        v[i] = __ldcs(&data[(base + (size_t)s_src[r + i]) * 32 + lane]);

    const size_t o = (base + (size_t)(row0 + r)) * 32 + lane;
    #pragma unroll
    for (int i = 0; i < ROWS_PER_WARP; ++i)
        __stcs(&out[o + (size_t)i * 32], v[i]);
}

extern "C" void kernel_launch(void* const* d_in, const int* in_sizes, int n_in,
                              void* d_out, int out_size) {
    // Identify which input is `sizes` (N_ITERS*BATCH elements) vs `data`.
    const void*   sizes = d_in[0];
    const float4* data  = (const float4*)d_in[1];
    if (n_in >= 2 && in_sizes[0] != N_ITERS * BATCH) {
        sizes = d_in[1];
        data  = (const float4*)d_in[0];
    }
    float4* out = (float4*)d_out;

    compute_ends_kernel<<<N_ITERS, 128>>>(sizes);

    dim3 grid(T_TOK / ROWS_PER_BLOCK, N_ITERS);
    seg_reverse_gather_kernel<<<grid, 256>>>(data, out);
}

// round 6
// speedup vs baseline: 1.2322x; 1.0079x over previous
#include <cuda_runtime.h>
#include <stdint.h>

#define N_ITERS 40
#define BATCH   128
#define T_TOK   32768
#define ROWS_PER_BLOCK 32
#define ROWS_PER_WARP  4

// Fused: each block recomputes its iteration's segment-end offsets inline
// (512B of sizes, L2-resident), then gathers 32 token rows.
// 256 threads/block. Threads 0-127 scan; threads 0-31 binary-search;
// each of the 8 warps moves 4 rows with 4 independent LDG.128 in flight.
__global__ __launch_bounds__(256) void seg_reverse_fused_kernel(
    const void* __restrict__ sizes_raw,
    const float4* __restrict__ data, float4* __restrict__ out) {
    __shared__ int s_ends[BATCH];
    __shared__ int s_src[ROWS_PER_BLOCK];
    __shared__ int s_warp[4];

    const int n    = blockIdx.y;
    const int tid  = threadIdx.x;
    const int lane = tid & 31;
    const int warp = tid >> 5;

    const int*       s32 = (const int*)sizes_raw;
    const long long* s64 = (const long long*)sizes_raw;

    // ---- inclusive scan of 128 segment sizes (threads 0-127) ----
    int v = 0;
    if (tid < BATCH) v = s32[n * BATCH + tid];
    #pragma unroll
    for (int d = 1; d < 32; d <<= 1) {
        int u = __shfl_up_sync(0xffffffffu, v, d);
        if (lane >= d) v += u;
    }
    if (tid < BATCH && lane == 31) s_warp[warp] = v;
    __syncthreads();
    int total = s_warp[0] + s_warp[1] + s_warp[2] + s_warp[3];

    if (total != T_TOK) {
        // sizes stored as int64: rescan using low word of each 8B element.
        __syncthreads();
        v = 0;
        if (tid < BATCH) v = (int)s64[(size_t)n * BATCH + tid];
        #pragma unroll
        for (int d = 1; d < 32; d <<= 1) {
            int u = __shfl_up_sync(0xffffffffu, v, d);
            if (lane >= d) v += u;
        }
        if (tid < BATCH && lane == 31) s_warp[warp] = v;
        __syncthreads();
    }

    if (tid < BATCH) {
        int add = 0;
        #pragma unroll
        for (int w = 0; w < 3; ++w) if (w < warp) add += s_warp[w];
        s_ends[tid] = v + add;
    }
    __syncthreads();

    // ---- per-row source index: searchsorted(ends, t, 'right') ----
    const int row0 = blockIdx.x * ROWS_PER_BLOCK;
    if (tid < ROWS_PER_BLOCK) {
        const int t = row0 + tid;
        int lo = 0, hi = BATCH;
        #pragma unroll
        for (int s = 0; s < 8; ++s) {   // answer in [0,128] -> 8 bisect steps
            int mid = (lo + hi) >> 1;
            if (s_ends[mid] > t) hi = mid; else lo = mid + 1;
        }
        const int seg   = (lo < BATCH) ? lo : (BATCH - 1);
        const int end   = s_ends[seg];
        const int start = seg ? s_ends[seg - 1] : 0;
        int src = start + end - 1 - t;
        src = src < 0 ? 0 : (src >= T_TOK ? T_TOK - 1 : src);
        s_src[tid] = src;
    }
    __syncthreads();

    // ---- copy: 4 independent 512B row reads in flight, then 4 writes ----
    const size_t base = (size_t)n * T_TOK;
    const int r = warp * ROWS_PER_WARP;

    float4 v0 = __ldcs(&data[(base + (size_t)s_src[r + 0]) * 32 + lane]);
    float4 v1 = __ldcs(&data[(base + (size_t)s_src[r + 1]) * 32 + lane]);
    float4 v2 = __ldcs(&data[(base + (size_t)s_src[r + 2]) * 32 + lane]);
    float4 v3 = __ldcs(&data[(base + (size_t)s_src[r + 3]) * 32 + lane]);

    const size_t o = (base + (size_t)(row0 + r)) * 32 + lane;
    __stcs(&out[o +  0], v0);
    __stcs(&out[o + 32], v1);
    __stcs(&out[o + 64], v2);
    __stcs(&out[o + 96], v3);
}

extern "C" void kernel_launch(void* const* d_in, const int* in_sizes, int n_in,
                              void* d_out, int out_size) {
    // Identify which input is `sizes` (N_ITERS*BATCH elements) vs `data`.
    const void*   sizes = d_in[0];
    const float4* data  = (const float4*)d_in[1];
    if (n_in >= 2 && in_sizes[0] != N_ITERS * BATCH) {
        sizes = d_in[1];
        data  = (const float4*)d_in[0];
    }
    float4* out = (float4*)d_out;

    dim3 grid(T_TOK / ROWS_PER_BLOCK, N_ITERS);
    seg_reverse_fused_kernel<<<grid, 256>>>(sizes, data, out);
}

// round 7
// speedup vs baseline: 1.2342x; 1.0016x over previous
#include <cuda_runtime.h>
#include <stdint.h>

#define N_ITERS 40
#define BATCH   128
#define T_TOK   32768
#define BLOCK_THREADS  512
#define ROWS_PER_BLOCK 64
#define ROWS_PER_WARP  4

// Fused: each block recomputes its iteration's segment-end offsets inline
// (512B of sizes, L2-resident), then gathers 64 token rows.
// 512 threads/block. Threads 0-127 scan; threads 0-63 binary-search;
// each of the 16 warps moves 4 rows with 4 independent LDG.128 in flight.
__global__ __launch_bounds__(BLOCK_THREADS) void seg_reverse_fused_kernel(
    const void* __restrict__ sizes_raw,
    const float4* __restrict__ data, float4* __restrict__ out) {
    __shared__ int s_ends[BATCH];
    __shared__ int s_src[ROWS_PER_BLOCK];
    __shared__ int s_warp[4];

    const int n    = blockIdx.y;
    const int tid  = threadIdx.x;
    const int lane = tid & 31;
    const int warp = tid >> 5;

    const int*       s32 = (const int*)sizes_raw;
    const long long* s64 = (const long long*)sizes_raw;

    // ---- inclusive scan of 128 segment sizes (threads 0-127) ----
    int v = 0;
    if (tid < BATCH) v = s32[n * BATCH + tid];
    #pragma unroll
    for (int d = 1; d < 32; d <<= 1) {
        int u = __shfl_up_sync(0xffffffffu, v, d);
        if (lane >= d) v += u;
    }
    if (tid < BATCH && lane == 31) s_warp[warp] = v;
    __syncthreads();
    int total = s_warp[0] + s_warp[1] + s_warp[2] + s_warp[3];

    if (total != T_TOK) {
        // sizes stored as int64: rescan using low word of each 8B element.
        __syncthreads();
        v = 0;
        if (tid < BATCH) v = (int)s64[(size_t)n * BATCH + tid];
        #pragma unroll
        for (int d = 1; d < 32; d <<= 1) {
            int u = __shfl_up_sync(0xffffffffu, v, d);
            if (lane >= d) v += u;
        }
        if (tid < BATCH && lane == 31) s_warp[warp] = v;
        __syncthreads();
    }

    if (tid < BATCH) {
        int add = 0;
        #pragma unroll
        for (int w = 0; w < 3; ++w) if (w < warp) add += s_warp[w];
        s_ends[tid] = v + add;
    }
    __syncthreads();

    // ---- per-row source index: searchsorted(ends, t, 'right') ----
    const int row0 = blockIdx.x * ROWS_PER_BLOCK;
    if (tid < ROWS_PER_BLOCK) {
        const int t = row0 + tid;
        int lo = 0, hi = BATCH;
        #pragma unroll
        for (int s = 0; s < 8; ++s) {   // answer in [0,128] -> 8 bisect steps
            int mid = (lo + hi) >> 1;
            if (s_ends[mid] > t) hi = mid; else lo = mid + 1;
        }
        const int seg   = (lo < BATCH) ? lo : (BATCH - 1);
        const int end   = s_ends[seg];
        const int start = seg ? s_ends[seg - 1] : 0;
        int src = start + end - 1 - t;
        src = src < 0 ? 0 : (src >= T_TOK ? T_TOK - 1 : src);
        s_src[tid] = src;
    }
    __syncthreads();

    // ---- copy: 4 independent 512B row reads in flight, then 4 writes ----
    const size_t base = (size_t)n * T_TOK;
    const int r = warp * ROWS_PER_WARP;

    float4 v0 = __ldcs(&data[(base + (size_t)s_src[r + 0]) * 32 + lane]);
    float4 v1 = __ldcs(&data[(base + (size_t)s_src[r + 1]) * 32 + lane]);
    float4 v2 = __ldcs(&data[(base + (size_t)s_src[r + 2]) * 32 + lane]);
    float4 v3 = __ldcs(&data[(base + (size_t)s_src[r + 3]) * 32 + lane]);

    const size_t o = (base + (size_t)(row0 + r)) * 32 + lane;
    __stcs(&out[o +  0], v0);
    __stcs(&out[o + 32], v1);
    __stcs(&out[o + 64], v2);
    __stcs(&out[o + 96], v3);
}

extern "C" void kernel_launch(void* const* d_in, const int* in_sizes, int n_in,
                              void* d_out, int out_size) {
    // Identify which input is `sizes` (N_ITERS*BATCH elements) vs `data`.
    const void*   sizes = d_in[0];
    const float4* data  = (const float4*)d_in[1];
    if (n_in >= 2 && in_sizes[0] != N_ITERS * BATCH) {
        sizes = d_in[1];
        data  = (const float4*)d_in[0];
    }
    float4* out = (float4*)d_out;

    dim3 grid(T_TOK / ROWS_PER_BLOCK, N_ITERS);
    seg_reverse_fused_kernel<<<grid, BLOCK_THREADS>>>(sizes, data, out);
}